// round 6
// baseline (speedup 1.0000x reference)
#include <cuda_runtime.h>
#include <cstdint>

#define H        256
#define NG       2048
#define APG      64
#define GRID     148
#define TILE_F   (APG*H)       // 16384 floats per graph tile
#define TILE_B   (TILE_F*4)    // 65536 bytes
#define GMAX     14

// ---------------- device globals ----------------
__device__ float4 g_WcT4[64 * 1024];   // [kc][n] = (W_ih+W_hh)[n][4kc..4kc+3]
__device__ float  g_bc[1024];          // b_ih + b_hh
__device__ float  g_q0[H];
__device__ float  g_c0[H];

__device__ __forceinline__ float sigmoidf_(float v) {
    return 1.0f / (1.0f + __expf(-v));
}

// ---------------- prep ----------------
__global__ void prep_kernel(const float* __restrict__ W_ih,
                            const float* __restrict__ W_hh,
                            const float* __restrict__ b_ih,
                            const float* __restrict__ b_hh) {
    int idx = blockIdx.x * 256 + threadIdx.x;    // 65536 threads
    int kc = idx >> 10, n = idx & 1023;
    float4 a = *(const float4*)&W_ih[n * H + kc * 4];
    float4 b = *(const float4*)&W_hh[n * H + kc * 4];
    g_WcT4[idx] = make_float4(a.x + b.x, a.y + b.y, a.z + b.z, a.w + b.w);
    if (idx < 1024) g_bc[idx] = b_ih[idx] + b_hh[idx];
    if (idx < H) {
        float gi = b_ih[idx]       + b_hh[idx];
        float gg = b_ih[512 + idx] + b_hh[512 + idx];
        float go = b_ih[768 + idx] + b_hh[768 + idx];
        float c  = sigmoidf_(gi) * tanhf(gg);
        g_c0[idx] = c;
        g_q0[idx] = sigmoidf_(go) * tanhf(c);
    }
}

// ---------------- packed f32x2 helpers ----------------
__device__ __forceinline__ unsigned long long pack2(float lo, float hi) {
    unsigned long long r;
    asm("mov.b64 %0, {%1, %2};" : "=l"(r) : "f"(lo), "f"(hi));
    return r;
}
__device__ __forceinline__ void ffma2(unsigned long long& d,
                                      unsigned long long a,
                                      unsigned long long b) {
    asm("fma.rn.f32x2 %0, %1, %2, %0;" : "+l"(d) : "l"(a), "l"(b));
}
__device__ __forceinline__ float2 unpack2(unsigned long long v) {
    union { unsigned long long u; float2 f; } cv; cv.u = v; return cv.f;
}

// ---------------- SMEM layout (floats) ----------------
#define SM_FLOATS (32768 + 3584 + 3584 + 3584 + 7168 + 64 + 1024)
#define SM_BYTES  (SM_FLOATS * 4 + 16)

__global__ void __launch_bounds__(512, 1)
fused_kernel(const float* __restrict__ x, float* __restrict__ out) {
    extern __shared__ __align__(16) unsigned char smraw[];
    float* xs  = (float*)smraw;                  // [2][16384]
    float* hp  = xs  + 2 * TILE_F;               // [7][256] float2 (graph pairs)
    float* cst = hp  + 3584;                     // [14][256]
    float* qst = cst + GMAX * H;                 // [14][256]
    float* fo  = qst + GMAX * H;                 // 2x [7][256] float2
    float* sc  = fo  + 7168;                     // [64]
    float* red = sc  + 64;                       // [512] float2

    uint32_t smem_base;
    asm("{ .reg .u64 t; cvta.to.shared.u64 t, %1; cvt.u32.u64 %0, t; }"
        : "=r"(smem_base) : "l"(smraw));
    uint32_t mb0 = smem_base + SM_FLOATS * 4;
    uint32_t mb1 = mb0 + 8;

    int tid  = threadIdx.x;
    int lane = tid & 31;
    int w    = tid >> 5;
    int bid  = blockIdx.x;
    int G    = (NG - bid + GRID - 1) / GRID;     // 13 or 14
    int total = 3 * G;

    for (int idx = tid; idx < 3584; idx += 512) hp[idx] = 0.0f;
    for (int idx = tid; idx < GMAX * H; idx += 512) {
        cst[idx] = g_c0[idx & (H - 1)];
        qst[idx] = g_q0[idx & (H - 1)];
    }
    if (tid == 0) {
        asm volatile("mbarrier.init.shared.b64 [%0], 1;" :: "r"(mb0) : "memory");
        asm volatile("mbarrier.init.shared.b64 [%0], 1;" :: "r"(mb1) : "memory");
    }
    __syncthreads();

    float bci = 0, bcf = 0, bcg = 0, bco = 0;
    if (tid < H) {
        bci = g_bc[tid];       bcf = g_bc[256 + tid];
        bcg = g_bc[512 + tid]; bco = g_bc[768 + tid];
    }

    // TMA into SMEM for consumption slot j
    auto issue = [&](int j) {
        if (j < total && tid == 0) {
            int i2 = j % G;
            size_t g = (size_t)bid + (size_t)GRID * i2;
            uint32_t mbj = (j & 1) ? mb1 : mb0;
            uint32_t dst = smem_base + (uint32_t)(j & 1) * TILE_B;
            asm volatile("mbarrier.arrive.expect_tx.shared.b64 _, [%0], %1;"
                         :: "r"(mbj), "r"(TILE_B) : "memory");
            asm volatile("cp.async.bulk.shared::cta.global.mbarrier::complete_tx::bytes "
                         "[%0], [%1], %2, [%3];"
                         :: "r"(dst), "l"(x + g * TILE_F), "r"(TILE_B), "r"(mbj)
                         : "memory");
        }
    };
    // L2 prefetch of consumption slot j's tile
    auto prefetch = [&](int j) {
        if (j < total && tid == 0) {
            int i2 = j % G;
            size_t g = (size_t)bid + (size_t)GRID * i2;
            asm volatile("cp.async.bulk.prefetch.L2.global [%0], %1;"
                         :: "l"(x + g * TILE_F), "r"(TILE_B) : "memory");
        }
    };
    issue(0); issue(1);
    prefetch(2); prefetch(3);

    int ph0 = 0, ph1 = 0;
    int jj = 0;
    for (int s = 0; s < 3; ++s) {
        // ================= mat-vec + LSTM pointwise =================
        if (s > 0) {
            unsigned long long acc1[7], acc2[7];
            #pragma unroll
            for (int p = 0; p < 7; ++p) { acc1[p] = 0ull; acc2[p] = 0ull; }

            for (int kc = 0; kc < 64; ++kc) {
                // keep DRAM busy: L2-prefetch this step's upcoming tiles
                if ((kc & 7) == 0) prefetch(jj + 2 + (kc >> 3));

                float4 w1 = g_WcT4[kc * 1024 + tid];
                float4 w2 = g_WcT4[kc * 1024 + 512 + tid];
                unsigned long long w1x = pack2(w1.x, w1.x), w1y = pack2(w1.y, w1.y);
                unsigned long long w1z = pack2(w1.z, w1.z), w1w = pack2(w1.w, w1.w);
                unsigned long long w2x = pack2(w2.x, w2.x), w2y = pack2(w2.y, w2.y);
                unsigned long long w2z = pack2(w2.z, w2.z), w2w = pack2(w2.w, w2.w);
                #pragma unroll
                for (int p = 0; p < 7; ++p) {
                    ulonglong2 hA = *(const ulonglong2*)&hp[(p * 256 + kc * 4) * 2];
                    ulonglong2 hB = *(const ulonglong2*)&hp[(p * 256 + kc * 4 + 2) * 2];
                    ffma2(acc1[p], hA.x, w1x); ffma2(acc2[p], hA.x, w2x);
                    ffma2(acc1[p], hA.y, w1y); ffma2(acc2[p], hA.y, w2y);
                    ffma2(acc1[p], hB.x, w1z); ffma2(acc2[p], hB.x, w2z);
                    ffma2(acc1[p], hB.y, w1w); ffma2(acc2[p], hB.y, w2w);
                }
            }
            if (tid >= 256) {
                int f = tid - 256;
                #pragma unroll
                for (int p = 0; p < 7; ++p) {
                    *(unsigned long long*)&fo[(p * 256 + f) * 2]        = acc1[p];
                    *(unsigned long long*)&fo[3584 + (p * 256 + f) * 2] = acc2[p];
                }
            }
            __syncthreads();
            if (tid < H) {
                #pragma unroll
                for (int p = 0; p < 7; ++p) {
                    float2 iv = unpack2(acc1[p]);
                    float2 gv = unpack2(acc2[p]);
                    float2 fv = *(const float2*)&fo[(p * 256 + tid) * 2];
                    float2 ov = *(const float2*)&fo[3584 + (p * 256 + tid) * 2];
                    #pragma unroll
                    for (int l = 0; l < 2; ++l) {
                        int i = 2 * p + l;
                        if (i >= G) continue;
                        float gi = (l ? iv.y : iv.x) + bci;
                        float gf = (l ? fv.y : fv.x) + bcf;
                        float gg = (l ? gv.y : gv.x) + bcg;
                        float go = (l ? ov.y : ov.x) + bco;
                        float cold = cst[i * H + tid];
                        float cn = sigmoidf_(gf) * cold + sigmoidf_(gi) * tanhf(gg);
                        float qn = sigmoidf_(go) * tanhf(cn);
                        cst[i * H + tid] = cn;
                        qst[i * H + tid] = qn;
                        if (s == 2) {
                            size_t g = (size_t)bid + (size_t)GRID * i;
                            out[g * (2 * H) + tid] = qn;
                        }
                    }
                }
            }
            __syncthreads();
        }

        // ================= attention =================
        for (int i = 0; i < G; ++i, ++jj) {
            int buf = jj & 1;
            {
                uint32_t mbc = buf ? mb1 : mb0;
                int phc = buf ? ph1 : ph0;
                uint32_t done;
                do {
                    asm volatile(
                        "{ .reg .pred p; "
                        "mbarrier.try_wait.parity.acquire.cta.shared::cta.b64 p, [%1], %2, 0x989680; "
                        "selp.b32 %0, 1, 0, p; }"
                        : "=r"(done) : "r"(mbc), "r"(phc) : "memory");
                } while (!done);
                if (buf) ph1 ^= 1; else ph0 ^= 1;
            }
            __syncthreads();

            const float* X    = xs + buf * TILE_F;
            const float* qrow = qst + i * H;

            // scores: warp w -> atoms 4w..4w+3
            float4 q4a = *(const float4*)&qrow[4 * lane];
            float4 q4b = *(const float4*)&qrow[128 + 4 * lane];
            #pragma unroll
            for (int aa = 0; aa < 4; ++aa) {
                const float* row = X + (w * 4 + aa) * H;
                float4 xa = *(const float4*)&row[4 * lane];
                float4 xb = *(const float4*)&row[128 + 4 * lane];
                float p = xa.x * q4a.x + xa.y * q4a.y + xa.z * q4a.z + xa.w * q4a.w
                        + xb.x * q4b.x + xb.y * q4b.y + xb.z * q4b.z + xb.w * q4b.w;
                #pragma unroll
                for (int off = 16; off; off >>= 1)
                    p += __shfl_xor_sync(0xffffffffu, p, off);
                if (lane == 0) sc[w * 4 + aa] = p;
            }
            __syncthreads();

            // softmax over 64 (warp 0); other warps prefetch far ahead
            if (w == 0) {
                float v0 = sc[lane], v1 = sc[lane + 32];
                float mx = fmaxf(v0, v1);
                #pragma unroll
                for (int off = 16; off; off >>= 1)
                    mx = fmaxf(mx, __shfl_xor_sync(0xffffffffu, mx, off));
                float e0 = __expf(v0 - mx), e1 = __expf(v1 - mx);
                float ssum = e0 + e1;
                #pragma unroll
                for (int off = 16; off; off >>= 1)
                    ssum += __shfl_xor_sync(0xffffffffu, ssum, off);
                float inv = 1.0f / ssum;
                sc[lane]      = e0 * inv;
                sc[lane + 32] = e1 * inv;
            }
            __syncthreads();

            // weighted sum: thread -> feature pair, quarter of atoms
            {
                int jq = tid & 127;
                int qt = tid >> 7;
                float2 r2 = make_float2(0.0f, 0.0f);
                const float* Xq = X + qt * 16 * H + 2 * jq;
                #pragma unroll
                for (int a0 = 0; a0 < 16; ++a0) {
                    float sw = sc[qt * 16 + a0];
                    float2 xv = *(const float2*)&Xq[a0 * H];
                    r2.x = fmaf(sw, xv.x, r2.x);
                    r2.y = fmaf(sw, xv.y, r2.y);
                }
                *(float2*)&red[tid * 2] = r2;
            }
            __syncthreads();   // X fully consumed

            issue(jj + 2);     // refill this buffer NOW (one phase earlier)
            prefetch(jj + 4);  // keep L2 warm ahead of the TMA

            if (tid < 128) {
                float2 r0 = *(const float2*)&red[tid * 2];
                float2 r1 = *(const float2*)&red[(tid + 128) * 2];
                float2 r2 = *(const float2*)&red[(tid + 256) * 2];
                float2 r3 = *(const float2*)&red[(tid + 384) * 2];
                float2 rr = make_float2(r0.x + r1.x + r2.x + r3.x,
                                        r0.y + r1.y + r2.y + r3.y);
                int p = i >> 1, l = i & 1;
                hp[(p * 256 + 2 * tid)     * 2 + l] = rr.x;
                hp[(p * 256 + 2 * tid + 1) * 2 + l] = rr.y;
                if (s == 2) {
                    size_t g = (size_t)bid + (size_t)GRID * i;
                    *(float2*)&out[g * (2 * H) + H + 2 * tid] = rr;
                }
            }
            __syncthreads();
        }
    }
}

// ---------------- launch ----------------
extern "C" void kernel_launch(void* const* d_in, const int* in_sizes, int n_in,
                              void* d_out, int out_size) {
    const float* x    = (const float*)d_in[0];
    const float* W_ih = (const float*)d_in[3];
    const float* W_hh = (const float*)d_in[4];
    const float* b_ih = (const float*)d_in[5];
    const float* b_hh = (const float*)d_in[6];
    float* out = (float*)d_out;

    cudaFuncSetAttribute(fused_kernel,
                         cudaFuncAttributeMaxDynamicSharedMemorySize,
                         (int)SM_BYTES);

    prep_kernel<<<256, 256>>>(W_ih, W_hh, b_ih, b_hh);
    fused_kernel<<<GRID, 512, SM_BYTES>>>(x, out);
}